// round 9
// baseline (speedup 1.0000x reference)
#include <cuda_runtime.h>
#include <math.h>
#include <stdint.h>

// Fixed shapes
#define BN 8192
#define DN 2048
#define ROWB (DN * 4)          // 8192 bytes per row
#define TINV 10.0f             // 1/T, T = 0.1
#define NTHR 128               // 4 warps/block
#define WPB  (NTHR / 32)       // 4
#define NBLK 296               // 2 blocks/SM on 148 SMs
#define TOTW (NBLK * WPB)      // 1184 warps
#define NBUF 3                 // smem row buffers per warp

// Dynamic smem layout:
//  [0, WPB*NBUF*ROWB)            row buffers  (4*3*8192 = 98304 B)
//  [98304, 98304 + WPB*NBUF*8)   mbarriers    (96 B)
#define SMEM_BUFS   0
#define SMEM_MBARS  (WPB * NBUF * ROWB)
#define SMEM_DYN    (SMEM_MBARS + WPB * NBUF * 8 + 32)

// Scratch (device globals)
__device__ double g_partE[NBLK];
__device__ double g_partW[NBLK];
__device__ double g_partL[NBLK];
__device__ unsigned int g_count;

__device__ __forceinline__ float warp_sum(float v) {
    #pragma unroll
    for (int o = 16; o; o >>= 1) v += __shfl_xor_sync(0xffffffffu, v, o);
    return v;
}
__device__ __forceinline__ double warp_sum_d(double v) {
    #pragma unroll
    for (int o = 16; o; o >>= 1) v += __shfl_xor_sync(0xffffffffu, v, o);
    return v;
}
__device__ __forceinline__ uint32_t smem_u32(const void* p) {
    uint32_t a;
    asm("{ .reg .u64 t; cvta.to.shared.u64 t, %1; cvt.u32.u64 %0, t; }"
        : "=r"(a) : "l"(p));
    return a;
}
__device__ __forceinline__ void mbar_init(uint32_t mbar, uint32_t cnt) {
    asm volatile("mbarrier.init.shared.b64 [%0], %1;" :: "r"(mbar), "r"(cnt) : "memory");
}
__device__ __forceinline__ void issue_row(uint32_t dst, const void* src, uint32_t mbar) {
    asm volatile("mbarrier.arrive.expect_tx.shared.b64 _, [%0], %1;"
                 :: "r"(mbar), "r"((uint32_t)ROWB) : "memory");
    asm volatile("cp.async.bulk.shared::cluster.global.mbarrier::complete_tx::bytes "
                 "[%0], [%1], %2, [%3];"
                 :: "r"(dst), "l"(src), "r"((uint32_t)ROWB), "r"(mbar) : "memory");
}
__device__ __forceinline__ void mbar_wait(uint32_t mbar, int phase) {
    asm volatile(
        "{\n\t"
        ".reg .pred P;\n\t"
        "WL_%=:\n\t"
        "mbarrier.try_wait.parity.acquire.cta.shared::cta.b64 P, [%0], %1, 0x989680;\n\t"
        "@!P bra WL_%=;\n\t"
        "}"
        :: "r"(mbar), "r"(phase) : "memory");
}

__global__ void __launch_bounds__(NTHR, 2)
fused_kernel(const float* __restrict__ embed,
             const float* __restrict__ ee,
             const float* __restrict__ labels,
             float* __restrict__ out) {
    extern __shared__ char dsm[];
    __shared__ double redE[WPB], redW[WPB], redL[WPB];
    __shared__ bool   s_last;

    const int tid  = threadIdx.x;
    const int warp = tid >> 5;
    const int lane = tid & 31;
    const int wg   = blockIdx.x * WPB + warp;
    const uint32_t smem_base = smem_u32(dsm);

    // ---- init mbarriers (one thread each), sync once ----
    if (tid < WPB * NBUF) mbar_init(smem_base + SMEM_MBARS + tid * 8, 1);
    __syncthreads();

    // per-warp buffer/mbar addresses
    uint32_t bufa[NBUF], mba[NBUF];
    const float4* bufp[NBUF];
    #pragma unroll
    for (int b = 0; b < NBUF; b++) {
        int slot = warp * NBUF + b;
        bufa[b] = smem_base + SMEM_BUFS + slot * ROWB;
        mba[b]  = smem_base + SMEM_MBARS + slot * 8;
        bufp[b] = reinterpret_cast<const float4*>(dsm + SMEM_BUFS + (size_t)slot * ROWB);
    }

    const char* eeb = reinterpret_cast<const char*>(ee);
    const int base = wg;

    // ---- prologue: fill the pipeline (rows base, base+TOTW, base+2*TOTW) ----
    if (lane == 0) {
        #pragma unroll
        for (int b = 0; b < NBUF; b++) {
            long r = base + (long)b * TOTW;
            if (r < BN) issue_row(bufa[b], eeb + r * (long)ROWB, mba[b]);
        }
    }

    // ---- anchor into registers while first copies are in flight ----
    const float4* a4 = reinterpret_cast<const float4*>(embed);
    float4 areg[16];
    float na2 = 0.f;
    #pragma unroll
    for (int i = 0; i < 16; i++) {
        float4 a = a4[i * 32 + lane];
        areg[i] = a;
        na2 = fmaf(a.x, a.x, na2);
        na2 = fmaf(a.y, a.y, na2);
        na2 = fmaf(a.z, a.z, na2);
        na2 = fmaf(a.w, a.w, na2);
    }
    na2 = warp_sum(na2);
    const float norm0 = sqrtf(na2);
    const float inv   = 1.0f / fmaxf(norm0, 1e-12f);     // F.normalize
    const float naf   = fmaxf(norm0 * inv, 1e-6f);       // cos eps
    const float scale = TINV * inv / naf;                // neg = -scale*dot/nb

    // ---- main pipeline: wait -> compute -> reissue same buffer ----
    double E = 0.0, W = 0.0, L = 0.0;
    int b = 0, phbits = 0;
    for (long row = base; row < BN; row += TOTW) {
        mbar_wait(mba[b], (phbits >> b) & 1);
        phbits ^= (1 << b);

        const float4* xb = bufp[b];
        float d0 = 0.f, d1 = 0.f, m0 = 0.f, m1 = 0.f;
        #pragma unroll
        for (int i = 0; i < 16; i += 2) {
            float4 x0 = xb[(i + 0) * 32 + lane];
            float4 x1 = xb[(i + 1) * 32 + lane];
            float4 a0 = areg[i + 0];
            float4 a1 = areg[i + 1];
            d0 = fmaf(x0.x, a0.x, d0); d0 = fmaf(x0.y, a0.y, d0);
            d0 = fmaf(x0.z, a0.z, d0); d0 = fmaf(x0.w, a0.w, d0);
            m0 = fmaf(x0.x, x0.x, m0); m0 = fmaf(x0.y, x0.y, m0);
            m0 = fmaf(x0.z, x0.z, m0); m0 = fmaf(x0.w, x0.w, m0);
            d1 = fmaf(x1.x, a1.x, d1); d1 = fmaf(x1.y, a1.y, d1);
            d1 = fmaf(x1.z, a1.z, d1); d1 = fmaf(x1.w, a1.w, d1);
            m1 = fmaf(x1.x, x1.x, m1); m1 = fmaf(x1.y, x1.y, m1);
            m1 = fmaf(x1.z, x1.z, m1); m1 = fmaf(x1.w, x1.w, m1);
        }
        float dot = warp_sum(d0 + d1);
        float n2  = warp_sum(m0 + m1);

        // reissue this buffer for row + NBUF*TOTW (compute done -> safe)
        long nr = row + (long)NBUF * TOTW;
        if (lane == 0 && nr < BN)
            issue_row(bufa[b], eeb + nr * (long)ROWB, mba[b]);

        if (lane == 0 && row != 0) {
            float nb  = fmaxf(sqrtf(n2), 1e-6f);
            float neg = -scale * dot / nb;
            float lj  = labels[row];
            E += (double)expf(neg);
            W += (double)lj * (double)neg;
            L += (double)lj;
        }
        b = (b == NBUF - 1) ? 0 : b + 1;
    }

    // ---- block partials -> scratch ----
    if (lane == 0) { redE[warp] = E; redW[warp] = W; redL[warp] = L; }
    __syncthreads();
    if (warp == 0) {
        double e = (lane < WPB) ? redE[lane] : 0.0;
        double w = (lane < WPB) ? redW[lane] : 0.0;
        double l = (lane < WPB) ? redL[lane] : 0.0;
        e = warp_sum_d(e); w = warp_sum_d(w); l = warp_sum_d(l);
        if (lane == 0) {
            g_partE[blockIdx.x] = e;
            g_partW[blockIdx.x] = w;
            g_partL[blockIdx.x] = l;
            __threadfence();
            unsigned int c = atomicAdd(&g_count, 1u);
            s_last = (c == NBLK - 1);
        }
    }
    __syncthreads();

    // ---- last block reduces ALL NBLK partials (strided) and finalizes ----
    if (s_last) {
        double e = 0.0, w = 0.0, l = 0.0;
        for (int idx = tid; idx < NBLK; idx += NTHR) {
            e += g_partE[idx]; w += g_partW[idx]; l += g_partL[idx];
        }
        e = warp_sum_d(e); w = warp_sum_d(w); l = warp_sum_d(l);
        if (lane == 0) { redE[warp] = e; redW[warp] = w; redL[warp] = l; }
        __syncthreads();
        if (tid == 0) {
            double Et = 0, Wt = 0, Lt = 0;
            #pragma unroll
            for (int i = 0; i < WPB; i++) { Et += redE[i]; Wt += redW[i]; Lt += redL[i]; }
            double l0   = (double)labels[0];
            double E0   = 1e-12 + Et;
            double C0   = 1e-12 + l0 * Lt;
            double logE = log(E0);
            double L0   = (l0 / C0) * (logE * Lt - Wt);
            out[0] = (float)(L0 / (double)BN);
            g_count = 0;                                  // reset for replay
        }
    }
}

extern "C" void kernel_launch(void* const* d_in, const int* in_sizes, int n_in,
                              void* d_out, int out_size) {
    const float* embed         = (const float*)d_in[0];
    const float* embed_enhance = (const float*)d_in[1];
    const float* labels        = (const float*)d_in[2];
    float* out = (float*)d_out;

    cudaFuncSetAttribute(fused_kernel,
                         cudaFuncAttributeMaxDynamicSharedMemorySize, SMEM_DYN);
    fused_kernel<<<NBLK, NTHR, SMEM_DYN>>>(embed, embed_enhance, labels, out);
}

// round 10
// speedup vs baseline: 1.0493x; 1.0493x over previous
#include <cuda_runtime.h>
#include <math.h>
#include <stdint.h>

// Fixed shapes
#define BN 8192
#define DN 2048
#define ROWB (DN * 4)          // 8192 bytes/row
#define TINV 10.0f             // 1/T
#define NTHR 192               // 6 warps/block
#define WPB  (NTHR / 32)       // 6
#define NBLK 296               // 2 blocks/SM -> 12 warps/SM
#define TOTW (NBLK * WPB)      // 1776 warps
#define NBUF 2
#define SMEM_DYN (WPB * NBUF * ROWB)   // 96 KB

// Scratch
__device__ double g_partE[NBLK];
__device__ double g_partW[NBLK];
__device__ double g_partL[NBLK];
__device__ unsigned int g_count;

__device__ __forceinline__ float warp_sum(float v) {
    #pragma unroll
    for (int o = 16; o; o >>= 1) v += __shfl_xor_sync(0xffffffffu, v, o);
    return v;
}
__device__ __forceinline__ double warp_sum_d(double v) {
    #pragma unroll
    for (int o = 16; o; o >>= 1) v += __shfl_xor_sync(0xffffffffu, v, o);
    return v;
}
__device__ __forceinline__ uint32_t smem_u32(const void* p) {
    uint32_t a;
    asm("{ .reg .u64 t; cvta.to.shared.u64 t, %1; cvt.u32.u64 %0, t; }"
        : "=r"(a) : "l"(p));
    return a;
}
// One lane copies its own 16B x 16 slots of a row: row bytes [(i*32+lane)*16 .. +16)
__device__ __forceinline__ void issue_row_cp(uint32_t dst_base, const char* src_row, int lane) {
    #pragma unroll
    for (int i = 0; i < 16; i++) {
        uint32_t off = (uint32_t)(i * 32 + lane) * 16u;
        asm volatile("cp.async.cg.shared.global [%0], [%1], 16;"
                     :: "r"(dst_base + off), "l"(src_row + off) : "memory");
    }
}
__device__ __forceinline__ void cp_commit() {
    asm volatile("cp.async.commit_group;" ::: "memory");
}
__device__ __forceinline__ void cp_wait1() {
    asm volatile("cp.async.wait_group 1;" ::: "memory");
}

__global__ void __launch_bounds__(NTHR, 2)
fused_kernel(const float* __restrict__ embed,
             const float* __restrict__ ee,
             const float* __restrict__ labels,
             float* __restrict__ out) {
    extern __shared__ char dsm[];
    __shared__ double redE[WPB], redW[WPB], redL[WPB];
    __shared__ bool   s_last;

    const int tid  = threadIdx.x;
    const int warp = tid >> 5;
    const int lane = tid & 31;
    const int wg   = blockIdx.x * WPB + warp;

    const uint32_t smem_base = smem_u32(dsm);
    uint32_t bufa[NBUF];
    const float4* bufp[NBUF];
    #pragma unroll
    for (int b = 0; b < NBUF; b++) {
        int slot = warp * NBUF + b;
        bufa[b] = smem_base + (uint32_t)slot * ROWB;
        bufp[b] = reinterpret_cast<const float4*>(dsm + (size_t)slot * ROWB);
    }

    const char* eeb = reinterpret_cast<const char*>(ee);

    // ---- prologue: two groups (buffers 0,1); empty groups keep counts uniform ----
    {
        long r0 = wg;
        if (r0 < BN) issue_row_cp(bufa[0], eeb + r0 * (long)ROWB, lane);
        cp_commit();
        long r1 = wg + (long)TOTW;
        if (r1 < BN) issue_row_cp(bufa[1], eeb + r1 * (long)ROWB, lane);
        cp_commit();
    }

    // ---- anchor into registers while copies fly ----
    const float4* a4 = reinterpret_cast<const float4*>(embed);
    float4 areg[16];
    float na2 = 0.f;
    #pragma unroll
    for (int i = 0; i < 16; i++) {
        float4 a = a4[i * 32 + lane];
        areg[i] = a;
        na2 = fmaf(a.x, a.x, na2);
        na2 = fmaf(a.y, a.y, na2);
        na2 = fmaf(a.z, a.z, na2);
        na2 = fmaf(a.w, a.w, na2);
    }
    na2 = warp_sum(na2);
    const float norm0 = sqrtf(na2);
    const float inv   = 1.0f / fmaxf(norm0, 1e-12f);     // F.normalize
    const float naf   = fmaxf(norm0 * inv, 1e-6f);       // cos eps
    const float scale = TINV * inv / naf;

    // ---- pipeline: wait -> compute own-lane data -> reissue buffer ----
    double E = 0.0, W = 0.0, L = 0.0;
    int b = 0;
    for (long row = wg; row < BN; row += TOTW) {
        cp_wait1();            // oldest group (this buffer) complete
        __syncwarp();

        const float4* xb = bufp[b];
        float d0 = 0.f, d1 = 0.f, m0 = 0.f, m1 = 0.f;
        #pragma unroll
        for (int i = 0; i < 16; i += 2) {
            float4 x0 = xb[(i + 0) * 32 + lane];
            float4 x1 = xb[(i + 1) * 32 + lane];
            float4 a0 = areg[i + 0];
            float4 a1 = areg[i + 1];
            d0 = fmaf(x0.x, a0.x, d0); d0 = fmaf(x0.y, a0.y, d0);
            d0 = fmaf(x0.z, a0.z, d0); d0 = fmaf(x0.w, a0.w, d0);
            m0 = fmaf(x0.x, x0.x, m0); m0 = fmaf(x0.y, x0.y, m0);
            m0 = fmaf(x0.z, x0.z, m0); m0 = fmaf(x0.w, x0.w, m0);
            d1 = fmaf(x1.x, a1.x, d1); d1 = fmaf(x1.y, a1.y, d1);
            d1 = fmaf(x1.z, a1.z, d1); d1 = fmaf(x1.w, a1.w, d1);
            m1 = fmaf(x1.x, x1.x, m1); m1 = fmaf(x1.y, x1.y, m1);
            m1 = fmaf(x1.z, x1.z, m1); m1 = fmaf(x1.w, x1.w, m1);
        }
        // reissue this buffer for row + 2*TOTW; ALWAYS commit (uniform counts)
        __syncwarp();          // all lanes done reading before overwrite
        long nr = row + (long)NBUF * TOTW;
        if (nr < BN) issue_row_cp(bufa[b], eeb + nr * (long)ROWB, lane);
        cp_commit();

        float dot = warp_sum(d0 + d1);
        float n2  = warp_sum(m0 + m1);
        if (lane == 0 && row != 0) {
            float nb  = fmaxf(sqrtf(n2), 1e-6f);
            float neg = -scale * dot / nb;
            float lj  = labels[row];
            E += (double)expf(neg);
            W += (double)lj * (double)neg;
            L += (double)lj;
        }
        b ^= 1;
    }

    // ---- block partials -> scratch ----
    if (lane == 0) { redE[warp] = E; redW[warp] = W; redL[warp] = L; }
    __syncthreads();
    if (warp == 0) {
        double e = (lane < WPB) ? redE[lane] : 0.0;
        double w = (lane < WPB) ? redW[lane] : 0.0;
        double l = (lane < WPB) ? redL[lane] : 0.0;
        e = warp_sum_d(e); w = warp_sum_d(w); l = warp_sum_d(l);
        if (lane == 0) {
            g_partE[blockIdx.x] = e;
            g_partW[blockIdx.x] = w;
            g_partL[blockIdx.x] = l;
            __threadfence();
            unsigned int c = atomicAdd(&g_count, 1u);
            s_last = (c == NBLK - 1);
        }
    }
    __syncthreads();

    // ---- last block: strided reduce over ALL NBLK partials ----
    if (s_last) {
        double e = 0.0, w = 0.0, l = 0.0;
        for (int idx = tid; idx < NBLK; idx += NTHR) {
            e += g_partE[idx]; w += g_partW[idx]; l += g_partL[idx];
        }
        e = warp_sum_d(e); w = warp_sum_d(w); l = warp_sum_d(l);
        if (lane == 0) { redE[warp] = e; redW[warp] = w; redL[warp] = l; }
        __syncthreads();
        if (tid == 0) {
            double Et = 0, Wt = 0, Lt = 0;
            #pragma unroll
            for (int i = 0; i < WPB; i++) { Et += redE[i]; Wt += redW[i]; Lt += redL[i]; }
            double l0   = (double)labels[0];
            double E0   = 1e-12 + Et;
            double C0   = 1e-12 + l0 * Lt;
            double logE = log(E0);
            double L0   = (l0 / C0) * (logE * Lt - Wt);
            out[0] = (float)(L0 / (double)BN);
            g_count = 0;
        }
    }
}

extern "C" void kernel_launch(void* const* d_in, const int* in_sizes, int n_in,
                              void* d_out, int out_size) {
    const float* embed         = (const float*)d_in[0];
    const float* embed_enhance = (const float*)d_in[1];
    const float* labels        = (const float*)d_in[2];
    float* out = (float*)d_out;

    cudaFuncSetAttribute(fused_kernel,
                         cudaFuncAttributeMaxDynamicSharedMemorySize, SMEM_DYN);
    fused_kernel<<<NBLK, NTHR, SMEM_DYN>>>(embed, embed_enhance, labels, out);
}

// round 11
// speedup vs baseline: 1.2060x; 1.1493x over previous
#include <cuda_runtime.h>
#include <math.h>

// Fixed shapes
#define BN 8192
#define DN 2048
#define TINV 10.0f            // 1/T, T = 0.1
#define NTHR 256              // 8 warps/block
#define WPB  (NTHR / 32)
#define NBLK 296              // 2 blocks/SM on 148 SMs
#define TOTW (NBLK * WPB)     // 2368 warps

// Scratch (device globals)
__device__ double g_partE[NBLK];
__device__ double g_partW[NBLK];
__device__ double g_partL[NBLK];
__device__ unsigned int g_count;

__device__ __forceinline__ float warp_sum(float v) {
    #pragma unroll
    for (int o = 16; o; o >>= 1) v += __shfl_xor_sync(0xffffffffu, v, o);
    return v;
}
__device__ __forceinline__ double warp_sum_d(double v) {
    #pragma unroll
    for (int o = 16; o; o >>= 1) v += __shfl_xor_sync(0xffffffffu, v, o);
    return v;
}

__global__ void __launch_bounds__(NTHR, 2)
fused_kernel(const float* __restrict__ embed,
             const float* __restrict__ ee,
             const float* __restrict__ labels,
             float* __restrict__ out) {
    __shared__ float4  sa[DN / 4];            // raw anchor, 8 KB
    __shared__ float   redf[WPB];
    __shared__ double  redE[WPB], redW[WPB], redL[WPB];
    __shared__ bool    s_last;

    const int tid  = threadIdx.x;
    const int warp = tid >> 5;
    const int lane = tid & 31;
    const int wg   = blockIdx.x * WPB + warp;

    // ---- Stage anchor into shared + ||e0||^2 partials; ONE sync. ----
    const float4* e4 = reinterpret_cast<const float4*>(embed);
    float na2p = 0.f;
    #pragma unroll
    for (int i = 0; i < (DN / 4) / NTHR; i++) {     // 2 iterations
        float4 v = e4[i * NTHR + tid];
        sa[i * NTHR + tid] = v;
        na2p = fmaf(v.x, v.x, na2p);
        na2p = fmaf(v.y, v.y, na2p);
        na2p = fmaf(v.z, v.z, na2p);
        na2p = fmaf(v.w, v.w, na2p);
    }
    na2p = warp_sum(na2p);
    if (lane == 0) redf[warp] = na2p;
    __syncthreads();

    float anorm2 = 0.f;
    #pragma unroll
    for (int i = 0; i < WPB; i++) anorm2 += redf[i];
    const float norm0 = sqrtf(anorm2);
    const float inv   = 1.0f / fmaxf(norm0, 1e-12f);     // F.normalize
    const float na    = fmaxf(norm0 * inv, 1e-6f);       // cos eps
    const float scale = TINV * inv / na;                 // neg = -scale*dot/nb

    // ---- Stream: front-batched 16x LDG.128.CV per row (no L1 allocation,
    //      bypasses the per-SM outstanding-miss cap). ----
    double E = 0.0, W = 0.0, L = 0.0;
    for (int row = wg; row < BN; row += TOTW) {
        const float4* x4 = reinterpret_cast<const float4*>(ee + (size_t)row * DN);

        // Phase A: batch ALL 16 .cv loads, no consumers in between.
        float4 x[16];
        #pragma unroll
        for (int i = 0; i < 16; i++) x[i] = __ldcv(&x4[i * 32 + lane]);

        // Phase B: FMA against smem anchor; 4 split accumulators each.
        float d0 = 0.f, d1 = 0.f, d2 = 0.f, d3 = 0.f;
        float m0 = 0.f, m1 = 0.f, m2 = 0.f, m3 = 0.f;
        #pragma unroll
        for (int i = 0; i < 16; i += 4) {
            float4 a0 = sa[(i + 0) * 32 + lane];
            float4 a1 = sa[(i + 1) * 32 + lane];
            float4 a2 = sa[(i + 2) * 32 + lane];
            float4 a3 = sa[(i + 3) * 32 + lane];
            d0 = fmaf(x[i+0].x, a0.x, d0); d0 = fmaf(x[i+0].y, a0.y, d0);
            d0 = fmaf(x[i+0].z, a0.z, d0); d0 = fmaf(x[i+0].w, a0.w, d0);
            m0 = fmaf(x[i+0].x, x[i+0].x, m0); m0 = fmaf(x[i+0].y, x[i+0].y, m0);
            m0 = fmaf(x[i+0].z, x[i+0].z, m0); m0 = fmaf(x[i+0].w, x[i+0].w, m0);
            d1 = fmaf(x[i+1].x, a1.x, d1); d1 = fmaf(x[i+1].y, a1.y, d1);
            d1 = fmaf(x[i+1].z, a1.z, d1); d1 = fmaf(x[i+1].w, a1.w, d1);
            m1 = fmaf(x[i+1].x, x[i+1].x, m1); m1 = fmaf(x[i+1].y, x[i+1].y, m1);
            m1 = fmaf(x[i+1].z, x[i+1].z, m1); m1 = fmaf(x[i+1].w, x[i+1].w, m1);
            d2 = fmaf(x[i+2].x, a2.x, d2); d2 = fmaf(x[i+2].y, a2.y, d2);
            d2 = fmaf(x[i+2].z, a2.z, d2); d2 = fmaf(x[i+2].w, a2.w, d2);
            m2 = fmaf(x[i+2].x, x[i+2].x, m2); m2 = fmaf(x[i+2].y, x[i+2].y, m2);
            m2 = fmaf(x[i+2].z, x[i+2].z, m2); m2 = fmaf(x[i+2].w, x[i+2].w, m2);
            d3 = fmaf(x[i+3].x, a3.x, d3); d3 = fmaf(x[i+3].y, a3.y, d3);
            d3 = fmaf(x[i+3].z, a3.z, d3); d3 = fmaf(x[i+3].w, a3.w, d3);
            m3 = fmaf(x[i+3].x, x[i+3].x, m3); m3 = fmaf(x[i+3].y, x[i+3].y, m3);
            m3 = fmaf(x[i+3].z, x[i+3].z, m3); m3 = fmaf(x[i+3].w, x[i+3].w, m3);
        }
        float dot = warp_sum((d0 + d1) + (d2 + d3));
        float n2  = warp_sum((m0 + m1) + (m2 + m3));

        if (lane == 0 && row != 0) {
            float nb  = fmaxf(sqrtf(n2), 1e-6f);
            float neg = -scale * dot / nb;
            float lj  = labels[row];
            E += (double)expf(neg);
            W += (double)lj * (double)neg;
            L += (double)lj;
        }
    }

    // ---- Block partials -> scratch ----
    if (lane == 0) { redE[warp] = E; redW[warp] = W; redL[warp] = L; }
    __syncthreads();
    if (warp == 0) {
        double e = (lane < WPB) ? redE[lane] : 0.0;
        double w = (lane < WPB) ? redW[lane] : 0.0;
        double l = (lane < WPB) ? redL[lane] : 0.0;
        e = warp_sum_d(e); w = warp_sum_d(w); l = warp_sum_d(l);
        if (lane == 0) {
            g_partE[blockIdx.x] = e;
            g_partW[blockIdx.x] = w;
            g_partL[blockIdx.x] = l;
            __threadfence();
            unsigned int c = atomicAdd(&g_count, 1u);
            s_last = (c == NBLK - 1);
        }
    }
    __syncthreads();

    // ---- Last block reduces ALL NBLK partials (strided) and finalizes ----
    if (s_last) {
        double e = 0.0, w = 0.0, l = 0.0;
        for (int idx = tid; idx < NBLK; idx += NTHR) {
            e += g_partE[idx]; w += g_partW[idx]; l += g_partL[idx];
        }
        e = warp_sum_d(e); w = warp_sum_d(w); l = warp_sum_d(l);
        if (lane == 0) { redE[warp] = e; redW[warp] = w; redL[warp] = l; }
        __syncthreads();
        if (tid == 0) {
            double Et = 0, Wt = 0, Lt = 0;
            #pragma unroll
            for (int i = 0; i < WPB; i++) { Et += redE[i]; Wt += redW[i]; Lt += redL[i]; }
            double l0   = (double)labels[0];
            double E0   = 1e-12 + Et;
            double C0   = 1e-12 + l0 * Lt;
            double logE = log(E0);
            double L0   = (l0 / C0) * (logE * Lt - Wt);
            out[0] = (float)(L0 / (double)BN);
            g_count = 0;                                  // reset for replay
        }
    }
}

extern "C" void kernel_launch(void* const* d_in, const int* in_sizes, int n_in,
                              void* d_out, int out_size) {
    const float* embed         = (const float*)d_in[0];
    const float* embed_enhance = (const float*)d_in[1];
    const float* labels        = (const float*)d_in[2];
    float* out = (float*)d_out;

    fused_kernel<<<NBLK, NTHR>>>(embed, embed_enhance, labels, out);
}